// round 16
// baseline (speedup 1.0000x reference)
#include <cuda_runtime.h>
#include <cuda_bf16.h>
#include <math.h>

#define B_   32
#define T_   512
#define IND  512
#define U_   1024
#define G4   4096   // 4*U
#define NBLK 128
#define MROWS (B_ * T_)   // 16384

// ---------------- scratch (static device globals; no allocs allowed) ----------
__device__ __align__(16) float g_xproj[(size_t)MROWS * G4];      // 256 MB [b*T+t][4U]
__device__ unsigned g_count;
__device__ unsigned g_gen;

__device__ __align__(16) __nv_bfloat16 g_dataH[(size_t)MROWS * IND];  // 16 MB
__device__ __align__(16) __nv_bfloat16 g_dataL[(size_t)MROWS * IND];  // 16 MB
__device__ __align__(16) __nv_bfloat16 g_wxTH[(size_t)G4 * IND];      // 4 MB [n][k]
__device__ __align__(16) __nv_bfloat16 g_wxTL[(size_t)G4 * IND];      // 4 MB

// h feedback as bf16 hi/lo pairs, K-MAJOR [u][b] (coalesced staging), ping-pong
__device__ __align__(16) __nv_bfloat16 g_hH[2][U_ * B_];
__device__ __align__(16) __nv_bfloat16 g_hL[2][U_ * B_];

// ---------------- init + bf16 hi/lo conversions -------------------------------
__global__ void init_state() {
    int i = blockIdx.x * blockDim.x + threadIdx.x;
    if (i < U_ * B_) {
        g_hH[0][i] = __float2bfloat16(0.f);
        g_hL[0][i] = __float2bfloat16(0.f);
    }
}

__global__ void conv_data(const float* __restrict__ A) {
    size_t i = (size_t)blockIdx.x * blockDim.x + threadIdx.x;
    if (i < (size_t)MROWS * IND) {
        float x = A[i];
        __nv_bfloat16 hi = __float2bfloat16(x);
        g_dataH[i] = hi;
        g_dataL[i] = __float2bfloat16(x - __bfloat162float(hi));
    }
}

__global__ void conv_wxT(const float* __restrict__ Wx) {
    size_t i = (size_t)blockIdx.x * blockDim.x + threadIdx.x;   // i = n*512 + k
    if (i < (size_t)G4 * IND) {
        int n = (int)(i >> 9);
        int k = (int)(i & 511);
        float x = Wx[(size_t)k * G4 + n];
        __nv_bfloat16 hi = __float2bfloat16(x);
        g_wxTH[i] = hi;
        g_wxTL[i] = __float2bfloat16(x - __bfloat162float(hi));
    }
}

// ---------------- shared helpers ----------------------------------------------
__device__ __forceinline__ unsigned smem_u32(const void* p) {
    unsigned a;
    asm("{ .reg .u64 t; cvta.to.shared.u64 t, %1; cvt.u32.u64 %0, t; }"
        : "=r"(a) : "l"(p));
    return a;
}

#define LDM4(r0, r1, r2, r3, addr) \
    asm volatile("ldmatrix.sync.aligned.m8n8.x4.shared.b16 {%0,%1,%2,%3}, [%4];" \
        : "=r"(r0), "=r"(r1), "=r"(r2), "=r"(r3) : "r"(addr))

#define LDM4T(r0, r1, r2, r3, addr) \
    asm volatile("ldmatrix.sync.aligned.m8n8.x4.trans.shared.b16 {%0,%1,%2,%3}, [%4];" \
        : "=r"(r0), "=r"(r1), "=r"(r2), "=r"(r3) : "r"(addr))

#define MMA16816(d, a, b0, b1) \
    asm volatile("mma.sync.aligned.m16n8k16.row.col.f32.bf16.bf16.f32 " \
        "{%0,%1,%2,%3}, {%4,%5,%6,%7}, {%8,%9}, {%0,%1,%2,%3};" \
        : "+f"(d[0]), "+f"(d[1]), "+f"(d[2]), "+f"(d[3]) \
        : "r"(a[0]), "r"(a[1]), "r"(a[2]), "r"(a[3]), "r"(b0), "r"(b1))

#define CP16(dst, src) \
    asm volatile("cp.async.cg.shared.global [%0], [%1], 16;" \
        :: "r"(dst), "l"(src) : "memory")
#define CPCOMMIT() asm volatile("cp.async.commit_group;" ::: "memory")
#define CPWAIT(n)  asm volatile("cp.async.wait_group %0;" :: "n"(n) : "memory")

__device__ __forceinline__ float sigmoidf_(float x) {
    return 1.f / (1.f + __expf(-x));
}
__device__ __forceinline__ float tanhf_(float x) {
    return 2.f / (1.f + __expf(-2.f * x)) - 1.f;
}

// ---------------- Kernel 1: bf16x3 mma.sync GEMM, cp.async double-buffered ----
#define SA 40   // smem row stride in bf16
// dynamic smem: 2 buffers x 40960B; per buffer: Ah 0 | Al 10240 | Bh 20480 | Bl 30720
extern __shared__ __nv_bfloat16 smem_gd[];

__device__ __forceinline__ void gemm_stage(unsigned base, int mt, int nt,
                                           int ch, int tid) {
    const int k0 = ch * 32;
    #pragma unroll
    for (int i = 0; i < 2; i++) {
        int gidx = tid + i * 256;
        int row  = gidx >> 2;
        int kq   = gidx & 3;
        unsigned so = (unsigned)((row * SA + kq * 8) * 2);
        size_t ga = (size_t)(mt + row) * IND + k0 + kq * 8;
        size_t gb = (size_t)(nt + row) * IND + k0 + kq * 8;
        CP16(base + so,         (const char*)(g_dataH + ga));
        CP16(base + 10240 + so, (const char*)(g_dataL + ga));
        CP16(base + 20480 + so, (const char*)(g_wxTH + gb));
        CP16(base + 30720 + so, (const char*)(g_wxTL + gb));
    }
}

__global__ __launch_bounds__(256, 2) void gemm_bf16x3(const float* __restrict__ bias) {
    const int tid  = threadIdx.x;
    const int wid  = tid >> 5;
    const int lane = tid & 31;
    const int wm   = wid & 3;
    const int wn   = wid >> 2;
    const int nt   = blockIdx.x * 128;
    const int mt   = blockIdx.y * 128;

    const unsigned sb = smem_u32(smem_gd);

    float acc[2][8][4];
    #pragma unroll
    for (int i = 0; i < 2; i++)
        #pragma unroll
        for (int j = 0; j < 8; j++)
            #pragma unroll
            for (int q = 0; q < 4; q++) acc[i][j][q] = 0.f;

    const int aRow = wm * 32 + (lane & 15);
    const int aCol = (lane >> 4) * 8;
    const int bRow = wn * 64 + (lane & 7) + ((lane >> 4) << 3);
    const int bCol = ((lane >> 3) & 1) * 8;

    gemm_stage(sb, mt, nt, 0, tid);
    CPCOMMIT();

    for (int ch = 0; ch < 16; ch++) {
        if (ch < 15) {
            gemm_stage(sb + (unsigned)(((ch + 1) & 1) * 40960), mt, nt, ch + 1, tid);
            CPCOMMIT();
            CPWAIT(1);
        } else {
            CPWAIT(0);
        }
        __syncthreads();

        const unsigned cb = sb + (unsigned)((ch & 1) * 40960);
        #pragma unroll
        for (int ks = 0; ks < 2; ks++) {
            unsigned ah[2][4], al[2][4];
            #pragma unroll
            for (int mi = 0; mi < 2; mi++) {
                unsigned off = (unsigned)(((aRow + mi * 16) * SA + ks * 16 + aCol) * 2);
                LDM4(ah[mi][0], ah[mi][1], ah[mi][2], ah[mi][3], cb + off);
                LDM4(al[mi][0], al[mi][1], al[mi][2], al[mi][3], cb + 10240 + off);
            }
            unsigned bh[4][4], bl[4][4];
            #pragma unroll
            for (int n4 = 0; n4 < 4; n4++) {
                unsigned off = (unsigned)(((bRow + n4 * 16) * SA + ks * 16 + bCol) * 2);
                LDM4(bh[n4][0], bh[n4][1], bh[n4][2], bh[n4][3], cb + 20480 + off);
                LDM4(bl[n4][0], bl[n4][1], bl[n4][2], bl[n4][3], cb + 30720 + off);
            }
            #pragma unroll
            for (int mi = 0; mi < 2; mi++)
                #pragma unroll
                for (int ni = 0; ni < 8; ni++) {
                    unsigned bh0 = bh[ni >> 1][(ni & 1) * 2];
                    unsigned bh1 = bh[ni >> 1][(ni & 1) * 2 + 1];
                    unsigned bl0 = bl[ni >> 1][(ni & 1) * 2];
                    unsigned bl1 = bl[ni >> 1][(ni & 1) * 2 + 1];
                    MMA16816(acc[mi][ni], ah[mi], bh0, bh1);
                    MMA16816(acc[mi][ni], ah[mi], bl0, bl1);
                    MMA16816(acc[mi][ni], al[mi], bh0, bh1);
                }
        }
        __syncthreads();
    }

    const int row0 = mt + wm * 32 + (lane >> 2);
    const int col0 = nt + wn * 64 + (lane & 3) * 2;
    #pragma unroll
    for (int mi = 0; mi < 2; mi++)
        #pragma unroll
        for (int ni = 0; ni < 8; ni++) {
            int c = col0 + ni * 8;
            float bv0 = __ldg(bias + c);
            float bv1 = __ldg(bias + c + 1);
            int r = row0 + mi * 16;
            *(float2*)(g_xproj + (size_t)r * G4 + c) =
                make_float2(acc[mi][ni][0] + bv0, acc[mi][ni][1] + bv1);
            *(float2*)(g_xproj + (size_t)(r + 8) * G4 + c) =
                make_float2(acc[mi][ni][2] + bv0, acc[mi][ni][3] + bv1);
        }
}

// ---------------- Kernel 2: persistent tensor-core LSTM recurrence ------------
// (4720us-proven structure; only change: out[] store moved into barrier window)
extern __shared__ unsigned char smem_rec[];

#define SWS 1032
#define HST 80      // staged h row stride bytes (40 bf16)

__device__ __forceinline__ void stage_load(
    const __nv_bfloat16* hH, const __nv_bfloat16* hL, int kp, int lane, uint4 v[4])
{
    const uint4* sH = (const uint4*)(hH + (size_t)kp * B_);
    const uint4* sL = (const uint4*)(hL + (size_t)kp * B_);
    v[0] = __ldcg(sH + lane);
    v[1] = __ldcg(sH + lane + 32);
    v[2] = __ldcg(sL + lane);
    v[3] = __ldcg(sL + lane + 32);
}
__device__ __forceinline__ void stage_store(unsigned char* buf, int lane, const uint4 v[4])
{
    unsigned off = (unsigned)((lane >> 2) * HST + (lane & 3) * 16);
    *(uint4*)(buf + off)              = v[0];
    *(uint4*)(buf + off + 8 * HST)    = v[1];
    *(uint4*)(buf + 1280 + off)           = v[2];
    *(uint4*)(buf + 1280 + off + 8 * HST) = v[3];
}

__global__ __launch_bounds__(256) void lstm_tensor(
    const float* __restrict__ Wh,   // [1024][4096]
    float* __restrict__ out)        // [32][512][1024]
{
    __nv_bfloat16* wsH = (__nv_bfloat16*)smem_rec;
    __nv_bfloat16* wsL = (__nv_bfloat16*)(smem_rec + 66048);
    unsigned char* hbufs = smem_rec + 132096;
    float* part = (float*)(smem_rec + 193536);

    const int tid  = threadIdx.x;
    const int w    = tid >> 5;
    const int lane = tid & 31;
    const int u0   = blockIdx.x * 8;

    // ---- load + split + transpose this block's Wh slice (once) ----
    for (int i = tid; i < 32 * 1024; i += 256) {
        int n = i & 31;
        int k = i >> 5;
        int col = (n >> 3) * U_ + u0 + (n & 7);
        float v = Wh[(size_t)k * G4 + col];
        __nv_bfloat16 hi = __float2bfloat16(v);
        wsH[n * SWS + k] = hi;
        wsL[n * SWS + k] = __float2bfloat16(v - __bfloat162float(hi));
    }

    const int eb = tid >> 3;        // epilogue batch
    const int eu = tid & 7;         // epilogue unit
    float c_reg = 0.f;

    unsigned my_gen = *(volatile unsigned*)&g_gen;
    __syncthreads();

    unsigned char* myHbuf = hbufs + w * 7680;
    const unsigned hbA = smem_u32(myHbuf);
    const unsigned aOffT = (unsigned)((((lane & 7) + ((lane >> 4) << 3)) * HST)
                                      + (((lane >> 3) & 1) * 16));
    const unsigned wsHb = smem_u32(wsH);
    const unsigned wsLb = smem_u32(wsL);
    const int bRow = (lane & 7) + ((lane >> 4) << 3);
    const int bColSel = ((lane >> 3) & 1) * 8;

    for (int t = 0; t < T_; t++) {
        const __nv_bfloat16* __restrict__ hH = g_hH[t & 1];
        const __nv_bfloat16* __restrict__ hL = g_hL[t & 1];

        const float* xp = g_xproj + ((size_t)eb * T_ + t) * G4 + u0 + eu;
        float xpv0 = __ldg(xp);
        float xpv1 = __ldg(xp + U_);
        float xpv2 = __ldg(xp + 2 * U_);
        float xpv3 = __ldg(xp + 3 * U_);

        float acc[2][4][4];
        #pragma unroll
        for (int i = 0; i < 2; i++)
            #pragma unroll
            for (int j = 0; j < 4; j++)
                #pragma unroll
                for (int q = 0; q < 4; q++) acc[i][j][q] = 0.f;

        // prologue: stage phases 0,1 into ring slots 0,1
        {
            uint4 v0[4], v1[4];
            stage_load(hH, hL, w * 16, lane, v0);
            stage_load(hH, hL, 128 + w * 16, lane, v1);
            stage_store(myHbuf, lane, v0);
            stage_store(myHbuf + 2560, lane, v1);
            __syncwarp();
        }

        #pragma unroll
        for (int p = 0; p < 8; p++) {
            uint4 vn[4];
            if (p < 6)
                stage_load(hH, hL, (p + 2) * 128 + w * 16, lane, vn);

            const unsigned sbase = hbA + (unsigned)((p % 3) * 2560);
            unsigned ah[2][4], al[2][4];
            LDM4T(ah[0][0], ah[0][1], ah[0][2], ah[0][3], sbase + aOffT);
            LDM4T(ah[1][0], ah[1][1], ah[1][2], ah[1][3], sbase + aOffT + 32);
            LDM4T(al[0][0], al[0][1], al[0][2], al[0][3], sbase + 1280 + aOffT);
            LDM4T(al[1][0], al[1][1], al[1][2], al[1][3], sbase + 1280 + aOffT + 32);

            const int kabs = p * 128 + w * 16 + bColSel;
            unsigned bh[2][4], bl[2][4];
            #pragma unroll
            for (int n4 = 0; n4 < 2; n4++) {
                unsigned off = (unsigned)(((bRow + n4 * 16) * SWS + kabs) * 2);
                LDM4(bh[n4][0], bh[n4][1], bh[n4][2], bh[n4][3], wsHb + off);
                LDM4(bl[n4][0], bl[n4][1], bl[n4][2], bl[n4][3], wsLb + off);
            }

            #pragma unroll
            for (int mi = 0; mi < 2; mi++)
                #pragma unroll
                for (int ni = 0; ni < 4; ni++) {
                    unsigned b0h = bh[ni >> 1][(ni & 1) * 2];
                    unsigned b1h = bh[ni >> 1][(ni & 1) * 2 + 1];
                    unsigned b0l = bl[ni >> 1][(ni & 1) * 2];
                    unsigned b1l = bl[ni >> 1][(ni & 1) * 2 + 1];
                    MMA16816(acc[mi][ni], ah[mi], b0h, b1h);
                    MMA16816(acc[mi][ni], ah[mi], b0l, b1l);
                    MMA16816(acc[mi][ni], al[mi], b0h, b1h);
                }

            if (p < 6)
                stage_store(myHbuf + ((p + 2) % 3) * 2560, lane, vn);
            __syncwarp();
        }

        // ---- publish partials: part[w][row][col], stride 34 ----
        {
            float* pw = part + w * (32 * 34);
            const int pr = lane >> 2;
            const int pc = (lane & 3) * 2;
            #pragma unroll
            for (int mi = 0; mi < 2; mi++)
                #pragma unroll
                for (int ni = 0; ni < 4; ni++) {
                    int r = mi * 16 + pr;
                    int c = ni * 8 + pc;
                    pw[r * 34 + c]           = acc[mi][ni][0];
                    pw[r * 34 + c + 1]       = acc[mi][ni][1];
                    pw[(r + 8) * 34 + c]     = acc[mi][ni][2];
                    pw[(r + 8) * 34 + c + 1] = acc[mi][ni][3];
                }
        }
        __syncthreads();

        // ---- epilogue: thread = (eb, eu) ----
        float h_val;
        {
            float gate[4];
            #pragma unroll
            for (int g2 = 0; g2 < 4; g2++) {
                float s = 0.f;
                #pragma unroll
                for (int w2 = 0; w2 < 8; w2++)
                    s += part[w2 * (32 * 34) + eb * 34 + g2 * 8 + eu];
                gate[g2] = s;
            }
            gate[0] += xpv0;
            gate[1] += xpv1;
            gate[2] += xpv2;
            gate[3] += xpv3;

            float ig = sigmoidf_(gate[0]);
            float fg = sigmoidf_(gate[1]);
            float gv = tanhf_(gate[2]);
            float og = sigmoidf_(gate[3]);

            c_reg = fg * c_reg + ig * gv;
            h_val = og * tanhf_(c_reg);

            __nv_bfloat16 hhi = __float2bfloat16(h_val);
            g_hH[(t + 1) & 1][(u0 + eu) * B_ + eb] = hhi;
            g_hL[(t + 1) & 1][(u0 + eu) * B_ + eb] =
                __float2bfloat16(h_val - __bfloat162float(hhi));
        }

        // ---- grid barrier; out[] store overlapped with the poll ----
        __syncthreads();
        if (tid == 0) {
            out[((size_t)eb * T_ + t) * U_ + u0 + eu] = h_val;
            __threadfence();
            if (atomicAdd(&g_count, 1u) == NBLK - 1) {
                atomicExch(&g_count, 0u);
                __threadfence();
                atomicAdd(&g_gen, 1u);
            } else {
                while (*(volatile unsigned*)&g_gen == my_gen) {}
            }
            my_gen++;
        } else {
            out[((size_t)eb * T_ + t) * U_ + u0 + eu] = h_val;
        }
        __syncthreads();
    }
}

// ---------------- launch ------------------------------------------------------
extern "C" void kernel_launch(void* const* d_in, const int* in_sizes, int n_in,
                              void* d_out, int out_size) {
    const float* data = (const float*)d_in[0];   // [32,512,512]
    const float* Wx   = (const float*)d_in[1];   // [512,4096]
    const float* Wh   = (const float*)d_in[2];   // [1024,4096]
    const float* bias = (const float*)d_in[3];   // [4096]
    float* out = (float*)d_out;                  // [32,512,1024]

    const int smem_rec_bytes = 228352;           // 223 KB
    cudaFuncSetAttribute(lstm_tensor,
                         cudaFuncAttributeMaxDynamicSharedMemorySize, smem_rec_bytes);
    const int smem_gemm_bytes = 2 * 40960;       // 80 KB (double-buffered)
    cudaFuncSetAttribute(gemm_bf16x3,
                         cudaFuncAttributeMaxDynamicSharedMemorySize, smem_gemm_bytes);

    init_state<<<32, 1024>>>();
    conv_data<<<(MROWS * IND) / 256, 256>>>(data);
    conv_wxT<<<(G4 * IND) / 256, 256>>>(Wx);

    dim3 ggrid(G4 / 128, MROWS / 128);           // (32, 128)
    gemm_bf16x3<<<ggrid, 256, smem_gemm_bytes>>>(bias);

    lstm_tensor<<<NBLK, 256, smem_rec_bytes>>>(Wh, out);
}

// round 17
// speedup vs baseline: 1.0513x; 1.0513x over previous
#include <cuda_runtime.h>
#include <cuda_bf16.h>
#include <math.h>

#define B_   32
#define T_   512
#define IND  512
#define U_   1024
#define G4   4096   // 4*U
#define NBLK 128
#define MROWS (B_ * T_)   // 16384

// ---------------- scratch (static device globals; no allocs allowed) ----------
__device__ __align__(16) float g_xproj[(size_t)MROWS * G4];      // 256 MB [b*T+t][4U]
__device__ unsigned g_count;
__device__ unsigned g_gen;

__device__ __align__(16) __nv_bfloat16 g_dataH[(size_t)MROWS * IND];  // 16 MB
__device__ __align__(16) __nv_bfloat16 g_dataL[(size_t)MROWS * IND];  // 16 MB
__device__ __align__(16) __nv_bfloat16 g_wxTH[(size_t)G4 * IND];      // 4 MB [n][k]
__device__ __align__(16) __nv_bfloat16 g_wxTL[(size_t)G4 * IND];      // 4 MB

// h feedback as bf16 hi/lo pairs, K-MAJOR [u][b] (coalesced staging), ping-pong
__device__ __align__(16) __nv_bfloat16 g_hH[2][U_ * B_];
__device__ __align__(16) __nv_bfloat16 g_hL[2][U_ * B_];

// ---------------- init + bf16 hi/lo conversions -------------------------------
__global__ void init_state() {
    int i = blockIdx.x * blockDim.x + threadIdx.x;
    if (i < U_ * B_) {
        g_hH[0][i] = __float2bfloat16(0.f);
        g_hL[0][i] = __float2bfloat16(0.f);
    }
}

__global__ void conv_data(const float* __restrict__ A) {
    size_t i = (size_t)blockIdx.x * blockDim.x + threadIdx.x;
    if (i < (size_t)MROWS * IND) {
        float x = A[i];
        __nv_bfloat16 hi = __float2bfloat16(x);
        g_dataH[i] = hi;
        g_dataL[i] = __float2bfloat16(x - __bfloat162float(hi));
    }
}

__global__ void conv_wxT(const float* __restrict__ Wx) {
    size_t i = (size_t)blockIdx.x * blockDim.x + threadIdx.x;   // i = n*512 + k
    if (i < (size_t)G4 * IND) {
        int n = (int)(i >> 9);
        int k = (int)(i & 511);
        float x = Wx[(size_t)k * G4 + n];
        __nv_bfloat16 hi = __float2bfloat16(x);
        g_wxTH[i] = hi;
        g_wxTL[i] = __float2bfloat16(x - __bfloat162float(hi));
    }
}

// ---------------- shared helpers ----------------------------------------------
__device__ __forceinline__ unsigned smem_u32(const void* p) {
    unsigned a;
    asm("{ .reg .u64 t; cvta.to.shared.u64 t, %1; cvt.u32.u64 %0, t; }"
        : "=r"(a) : "l"(p));
    return a;
}

#define LDM4(r0, r1, r2, r3, addr) \
    asm volatile("ldmatrix.sync.aligned.m8n8.x4.shared.b16 {%0,%1,%2,%3}, [%4];" \
        : "=r"(r0), "=r"(r1), "=r"(r2), "=r"(r3) : "r"(addr))

#define LDM4T(r0, r1, r2, r3, addr) \
    asm volatile("ldmatrix.sync.aligned.m8n8.x4.trans.shared.b16 {%0,%1,%2,%3}, [%4];" \
        : "=r"(r0), "=r"(r1), "=r"(r2), "=r"(r3) : "r"(addr))

#define MMA16816(d, a, b0, b1) \
    asm volatile("mma.sync.aligned.m16n8k16.row.col.f32.bf16.bf16.f32 " \
        "{%0,%1,%2,%3}, {%4,%5,%6,%7}, {%8,%9}, {%0,%1,%2,%3};" \
        : "+f"(d[0]), "+f"(d[1]), "+f"(d[2]), "+f"(d[3]) \
        : "r"(a[0]), "r"(a[1]), "r"(a[2]), "r"(a[3]), "r"(b0), "r"(b1))

#define CP16(dst, src) \
    asm volatile("cp.async.cg.shared.global [%0], [%1], 16;" \
        :: "r"(dst), "l"(src) : "memory")
#define CPCOMMIT() asm volatile("cp.async.commit_group;" ::: "memory")
#define CPWAIT(n)  asm volatile("cp.async.wait_group %0;" :: "n"(n) : "memory")

__device__ __forceinline__ float sigmoidf_(float x) {
    return 1.f / (1.f + __expf(-x));
}
__device__ __forceinline__ float tanhf_(float x) {
    return 2.f / (1.f + __expf(-2.f * x)) - 1.f;
}

// ---------------- Kernel 1: bf16x3 mma.sync GEMM, cp.async double-buffered ----
// (R12-measured: 555us, tensor 61%)
#define SA 40   // smem row stride in bf16
// dynamic smem: 2 buffers x 40960B; per buffer: Ah 0 | Al 10240 | Bh 20480 | Bl 30720
extern __shared__ __nv_bfloat16 smem_gd[];

__device__ __forceinline__ void gemm_stage(unsigned base, int mt, int nt,
                                           int ch, int tid) {
    const int k0 = ch * 32;
    #pragma unroll
    for (int i = 0; i < 2; i++) {
        int gidx = tid + i * 256;
        int row  = gidx >> 2;
        int kq   = gidx & 3;
        unsigned so = (unsigned)((row * SA + kq * 8) * 2);
        size_t ga = (size_t)(mt + row) * IND + k0 + kq * 8;
        size_t gb = (size_t)(nt + row) * IND + k0 + kq * 8;
        CP16(base + so,         (const char*)(g_dataH + ga));
        CP16(base + 10240 + so, (const char*)(g_dataL + ga));
        CP16(base + 20480 + so, (const char*)(g_wxTH + gb));
        CP16(base + 30720 + so, (const char*)(g_wxTL + gb));
    }
}

__global__ __launch_bounds__(256, 2) void gemm_bf16x3(const float* __restrict__ bias) {
    const int tid  = threadIdx.x;
    const int wid  = tid >> 5;
    const int lane = tid & 31;
    const int wm   = wid & 3;
    const int wn   = wid >> 2;
    const int nt   = blockIdx.x * 128;
    const int mt   = blockIdx.y * 128;

    const unsigned sb = smem_u32(smem_gd);

    float acc[2][8][4];
    #pragma unroll
    for (int i = 0; i < 2; i++)
        #pragma unroll
        for (int j = 0; j < 8; j++)
            #pragma unroll
            for (int q = 0; q < 4; q++) acc[i][j][q] = 0.f;

    const int aRow = wm * 32 + (lane & 15);
    const int aCol = (lane >> 4) * 8;
    const int bRow = wn * 64 + (lane & 7) + ((lane >> 4) << 3);
    const int bCol = ((lane >> 3) & 1) * 8;

    gemm_stage(sb, mt, nt, 0, tid);
    CPCOMMIT();

    for (int ch = 0; ch < 16; ch++) {
        if (ch < 15) {
            gemm_stage(sb + (unsigned)(((ch + 1) & 1) * 40960), mt, nt, ch + 1, tid);
            CPCOMMIT();
            CPWAIT(1);
        } else {
            CPWAIT(0);
        }
        __syncthreads();

        const unsigned cb = sb + (unsigned)((ch & 1) * 40960);
        #pragma unroll
        for (int ks = 0; ks < 2; ks++) {
            unsigned ah[2][4], al[2][4];
            #pragma unroll
            for (int mi = 0; mi < 2; mi++) {
                unsigned off = (unsigned)(((aRow + mi * 16) * SA + ks * 16 + aCol) * 2);
                LDM4(ah[mi][0], ah[mi][1], ah[mi][2], ah[mi][3], cb + off);
                LDM4(al[mi][0], al[mi][1], al[mi][2], al[mi][3], cb + 10240 + off);
            }
            unsigned bh[4][4], bl[4][4];
            #pragma unroll
            for (int n4 = 0; n4 < 4; n4++) {
                unsigned off = (unsigned)(((bRow + n4 * 16) * SA + ks * 16 + bCol) * 2);
                LDM4(bh[n4][0], bh[n4][1], bh[n4][2], bh[n4][3], cb + 20480 + off);
                LDM4(bl[n4][0], bl[n4][1], bl[n4][2], bl[n4][3], cb + 30720 + off);
            }
            #pragma unroll
            for (int mi = 0; mi < 2; mi++)
                #pragma unroll
                for (int ni = 0; ni < 8; ni++) {
                    unsigned bh0 = bh[ni >> 1][(ni & 1) * 2];
                    unsigned bh1 = bh[ni >> 1][(ni & 1) * 2 + 1];
                    unsigned bl0 = bl[ni >> 1][(ni & 1) * 2];
                    unsigned bl1 = bl[ni >> 1][(ni & 1) * 2 + 1];
                    MMA16816(acc[mi][ni], ah[mi], bh0, bh1);
                    MMA16816(acc[mi][ni], ah[mi], bl0, bl1);
                    MMA16816(acc[mi][ni], al[mi], bh0, bh1);
                }
        }
        __syncthreads();
    }

    const int row0 = mt + wm * 32 + (lane >> 2);
    const int col0 = nt + wn * 64 + (lane & 3) * 2;
    #pragma unroll
    for (int mi = 0; mi < 2; mi++)
        #pragma unroll
        for (int ni = 0; ni < 8; ni++) {
            int c = col0 + ni * 8;
            float bv0 = __ldg(bias + c);
            float bv1 = __ldg(bias + c + 1);
            int r = row0 + mi * 16;
            *(float2*)(g_xproj + (size_t)r * G4 + c) =
                make_float2(acc[mi][ni][0] + bv0, acc[mi][ni][1] + bv1);
            *(float2*)(g_xproj + (size_t)(r + 8) * G4 + c) =
                make_float2(acc[mi][ni][2] + bv0, acc[mi][ni][3] + bv1);
        }
}

// ---------------- Kernel 2: persistent tensor-core LSTM recurrence ------------
// Bit-identical to the R11 4720us-proven version (out store in epilogue).
extern __shared__ unsigned char smem_rec[];

#define SWS 1032
#define HST 80      // staged h row stride bytes (40 bf16)

__device__ __forceinline__ void stage_load(
    const __nv_bfloat16* hH, const __nv_bfloat16* hL, int kp, int lane, uint4 v[4])
{
    const uint4* sH = (const uint4*)(hH + (size_t)kp * B_);
    const uint4* sL = (const uint4*)(hL + (size_t)kp * B_);
    v[0] = __ldcg(sH + lane);
    v[1] = __ldcg(sH + lane + 32);
    v[2] = __ldcg(sL + lane);
    v[3] = __ldcg(sL + lane + 32);
}
__device__ __forceinline__ void stage_store(unsigned char* buf, int lane, const uint4 v[4])
{
    unsigned off = (unsigned)((lane >> 2) * HST + (lane & 3) * 16);
    *(uint4*)(buf + off)              = v[0];
    *(uint4*)(buf + off + 8 * HST)    = v[1];
    *(uint4*)(buf + 1280 + off)           = v[2];
    *(uint4*)(buf + 1280 + off + 8 * HST) = v[3];
}

__global__ __launch_bounds__(256) void lstm_tensor(
    const float* __restrict__ Wh,   // [1024][4096]
    float* __restrict__ out)        // [32][512][1024]
{
    __nv_bfloat16* wsH = (__nv_bfloat16*)smem_rec;
    __nv_bfloat16* wsL = (__nv_bfloat16*)(smem_rec + 66048);
    unsigned char* hbufs = smem_rec + 132096;
    float* part = (float*)(smem_rec + 193536);

    const int tid  = threadIdx.x;
    const int w    = tid >> 5;
    const int lane = tid & 31;
    const int u0   = blockIdx.x * 8;

    // ---- load + split + transpose this block's Wh slice (once) ----
    for (int i = tid; i < 32 * 1024; i += 256) {
        int n = i & 31;
        int k = i >> 5;
        int col = (n >> 3) * U_ + u0 + (n & 7);
        float v = Wh[(size_t)k * G4 + col];
        __nv_bfloat16 hi = __float2bfloat16(v);
        wsH[n * SWS + k] = hi;
        wsL[n * SWS + k] = __float2bfloat16(v - __bfloat162float(hi));
    }

    const int eb = tid >> 3;        // epilogue batch
    const int eu = tid & 7;         // epilogue unit
    float c_reg = 0.f;

    unsigned my_gen = *(volatile unsigned*)&g_gen;
    __syncthreads();

    unsigned char* myHbuf = hbufs + w * 7680;
    const unsigned hbA = smem_u32(myHbuf);
    const unsigned aOffT = (unsigned)((((lane & 7) + ((lane >> 4) << 3)) * HST)
                                      + (((lane >> 3) & 1) * 16));
    const unsigned wsHb = smem_u32(wsH);
    const unsigned wsLb = smem_u32(wsL);
    const int bRow = (lane & 7) + ((lane >> 4) << 3);
    const int bColSel = ((lane >> 3) & 1) * 8;

    for (int t = 0; t < T_; t++) {
        const __nv_bfloat16* __restrict__ hH = g_hH[t & 1];
        const __nv_bfloat16* __restrict__ hL = g_hL[t & 1];

        const float* xp = g_xproj + ((size_t)eb * T_ + t) * G4 + u0 + eu;
        float xpv0 = __ldg(xp);
        float xpv1 = __ldg(xp + U_);
        float xpv2 = __ldg(xp + 2 * U_);
        float xpv3 = __ldg(xp + 3 * U_);

        float acc[2][4][4];
        #pragma unroll
        for (int i = 0; i < 2; i++)
            #pragma unroll
            for (int j = 0; j < 4; j++)
                #pragma unroll
                for (int q = 0; q < 4; q++) acc[i][j][q] = 0.f;

        // prologue: stage phases 0,1 into ring slots 0,1
        {
            uint4 v0[4], v1[4];
            stage_load(hH, hL, w * 16, lane, v0);
            stage_load(hH, hL, 128 + w * 16, lane, v1);
            stage_store(myHbuf, lane, v0);
            stage_store(myHbuf + 2560, lane, v1);
            __syncwarp();
        }

        #pragma unroll
        for (int p = 0; p < 8; p++) {
            uint4 vn[4];
            if (p < 6)
                stage_load(hH, hL, (p + 2) * 128 + w * 16, lane, vn);

            const unsigned sbase = hbA + (unsigned)((p % 3) * 2560);
            unsigned ah[2][4], al[2][4];
            LDM4T(ah[0][0], ah[0][1], ah[0][2], ah[0][3], sbase + aOffT);
            LDM4T(ah[1][0], ah[1][1], ah[1][2], ah[1][3], sbase + aOffT + 32);
            LDM4T(al[0][0], al[0][1], al[0][2], al[0][3], sbase + 1280 + aOffT);
            LDM4T(al[1][0], al[1][1], al[1][2], al[1][3], sbase + 1280 + aOffT + 32);

            const int kabs = p * 128 + w * 16 + bColSel;
            unsigned bh[2][4], bl[2][4];
            #pragma unroll
            for (int n4 = 0; n4 < 2; n4++) {
                unsigned off = (unsigned)(((bRow + n4 * 16) * SWS + kabs) * 2);
                LDM4(bh[n4][0], bh[n4][1], bh[n4][2], bh[n4][3], wsHb + off);
                LDM4(bl[n4][0], bl[n4][1], bl[n4][2], bl[n4][3], wsLb + off);
            }

            #pragma unroll
            for (int mi = 0; mi < 2; mi++)
                #pragma unroll
                for (int ni = 0; ni < 4; ni++) {
                    unsigned b0h = bh[ni >> 1][(ni & 1) * 2];
                    unsigned b1h = bh[ni >> 1][(ni & 1) * 2 + 1];
                    unsigned b0l = bl[ni >> 1][(ni & 1) * 2];
                    unsigned b1l = bl[ni >> 1][(ni & 1) * 2 + 1];
                    MMA16816(acc[mi][ni], ah[mi], b0h, b1h);
                    MMA16816(acc[mi][ni], ah[mi], b0l, b1l);
                    MMA16816(acc[mi][ni], al[mi], b0h, b1h);
                }

            if (p < 6)
                stage_store(myHbuf + ((p + 2) % 3) * 2560, lane, vn);
            __syncwarp();
        }

        // ---- publish partials: part[w][row][col], stride 34 ----
        {
            float* pw = part + w * (32 * 34);
            const int pr = lane >> 2;
            const int pc = (lane & 3) * 2;
            #pragma unroll
            for (int mi = 0; mi < 2; mi++)
                #pragma unroll
                for (int ni = 0; ni < 4; ni++) {
                    int r = mi * 16 + pr;
                    int c = ni * 8 + pc;
                    pw[r * 34 + c]           = acc[mi][ni][0];
                    pw[r * 34 + c + 1]       = acc[mi][ni][1];
                    pw[(r + 8) * 34 + c]     = acc[mi][ni][2];
                    pw[(r + 8) * 34 + c + 1] = acc[mi][ni][3];
                }
        }
        __syncthreads();

        // ---- epilogue: thread = (eb, eu) ----
        {
            float gate[4];
            #pragma unroll
            for (int g2 = 0; g2 < 4; g2++) {
                float s = 0.f;
                #pragma unroll
                for (int w2 = 0; w2 < 8; w2++)
                    s += part[w2 * (32 * 34) + eb * 34 + g2 * 8 + eu];
                gate[g2] = s;
            }
            gate[0] += xpv0;
            gate[1] += xpv1;
            gate[2] += xpv2;
            gate[3] += xpv3;

            float ig = sigmoidf_(gate[0]);
            float fg = sigmoidf_(gate[1]);
            float gv = tanhf_(gate[2]);
            float og = sigmoidf_(gate[3]);

            c_reg = fg * c_reg + ig * gv;
            float h = og * tanhf_(c_reg);

            __nv_bfloat16 hhi = __float2bfloat16(h);
            g_hH[(t + 1) & 1][(u0 + eu) * B_ + eb] = hhi;
            g_hL[(t + 1) & 1][(u0 + eu) * B_ + eb] =
                __float2bfloat16(h - __bfloat162float(hhi));
            out[((size_t)eb * T_ + t) * U_ + u0 + eu] = h;
        }

        // ---- grid barrier (R6-proven) ----
        __syncthreads();
        if (tid == 0) {
            __threadfence();
            if (atomicAdd(&g_count, 1u) == NBLK - 1) {
                atomicExch(&g_count, 0u);
                __threadfence();
                atomicAdd(&g_gen, 1u);
            } else {
                while (*(volatile unsigned*)&g_gen == my_gen) {}
            }
            my_gen++;
        }
        __syncthreads();
    }
}

// ---------------- launch ------------------------------------------------------
extern "C" void kernel_launch(void* const* d_in, const int* in_sizes, int n_in,
                              void* d_out, int out_size) {
    const float* data = (const float*)d_in[0];   // [32,512,512]
    const float* Wx   = (const float*)d_in[1];   // [512,4096]
    const float* Wh   = (const float*)d_in[2];   // [1024,4096]
    const float* bias = (const float*)d_in[3];   // [4096]
    float* out = (float*)d_out;                  // [32,512,1024]

    const int smem_rec_bytes = 228352;           // 223 KB
    cudaFuncSetAttribute(lstm_tensor,
                         cudaFuncAttributeMaxDynamicSharedMemorySize, smem_rec_bytes);
    const int smem_gemm_bytes = 2 * 40960;       // 80 KB (double-buffered)
    cudaFuncSetAttribute(gemm_bf16x3,
                         cudaFuncAttributeMaxDynamicSharedMemorySize, smem_gemm_bytes);

    init_state<<<32, 1024>>>();
    conv_data<<<(MROWS * IND) / 256, 256>>>(data);
    conv_wxT<<<(G4 * IND) / 256, 256>>>(Wx);

    dim3 ggrid(G4 / 128, MROWS / 128);           // (32, 128)
    gemm_bf16x3<<<ggrid, 256, smem_gemm_bytes>>>(bias);

    lstm_tensor<<<NBLK, 256, smem_rec_bytes>>>(Wh, out);
}